// round 15
// baseline (speedup 1.0000x reference)
#include <cuda_runtime.h>
#include <cuda_fp16.h>
#include <math.h>

namespace {

constexpr int DKP = 28;              // padded factor dim (25 -> 28), fp32 master
constexpr int NDIM = 2 * DKP;        // 56 floats per node (fp32 master)
constexpr int HS   = 32;             // half2 stride per node in fp16 mirror (128B aligned)
constexpr int TOTAL_NODES = 180000;  // 60000 + 30000 + 6*15000
constexpr int TOTAL_ROWS  = 270000;  // 60000 + 7*30000
constexpr int TOTAL_COLS  = 180000;  // 30000 + 60000 + 6*15000
constexpr int TOTAL_EDGES = 3800000; // 2*1e6 + 6*3e5
constexpr int OUT_ROWS = 90000;
constexpr int SCAN_ELEMS = 8192;     // per block (1024 thr x 8)
constexpr int SCAN_NBLK = (TOTAL_ROWS + SCAN_ELEMS - 1) / SCAN_ELEMS; // 33

__constant__ int c_EOFF[9] = {0,1000000,2000000,2300000,2600000,2900000,3200000,3500000,3800000};
__constant__ int c_ROFF[9] = {0,60000,90000,120000,150000,180000,210000,240000,270000};
__constant__ int c_COFF[9] = {0,30000,90000,105000,120000,135000,150000,165000,180000};
__constant__ int c_TOFF[9] = {0,60000,90000,105000,120000,135000,150000,165000,180000};
__constant__ int c_SRC[8]  = {0,1,1,1,1,1,1,1};
__constant__ int c_DST[8]  = {1,0,2,3,4,5,6,7};

__device__ float    g_emb [(size_t)TOTAL_NODES * NDIM + 16]; // fp32 master
__device__ unsigned g_embh[(size_t)TOTAL_NODES * HS];        // fp16 mirror: half2(k0[d],k1[d]), 128B rows
__device__ float    g_z   [(size_t)TOTAL_ROWS  * NDIM];      // transformed messages z'
__device__ float    g_p   [TOTAL_ROWS * 2];
__device__ __half   g_qh  [TOTAL_COLS * 2];                  // fp16 q, pair-packed
__device__ float    g_r   [TOTAL_ROWS * 2];
__device__ int      g_rowcnt[TOTAL_ROWS];        // re-zeroed by k_fill (invariant)
__device__ int      g_rowptr[TOTAL_ROWS + 1];
__device__ int      g_blocksum[SCAN_NBLK];
__device__ int      g_rank  [TOTAL_EDGES];
__device__ int2     g_cc    [TOTAL_EDGES];       // (pre-scaled mirror idx, pre-offset q idx)

struct Ptrs {
    const int*   edge[8];
    const float* embin[8];
    const float* Wtk;
    const float* at;
    const float* W;
    const float* q_rela;
};

__device__ __forceinline__ int find_seg8(const int* off, int x) {
    int e = 0;
    #pragma unroll
    for (int i = 1; i < 8; i++) e += (x >= off[i]);
    return e;
}

__device__ __forceinline__ float fast_tanh(float x) {
    float y;
    asm("tanh.approx.f32 %0, %1;" : "=f"(y) : "f"(x));
    return y;
}

__device__ __forceinline__ float dot25(const float* v, const float* a) {
    float s = 0.f;
    #pragma unroll
    for (int d = 0; d < 25; d++) s += v[d] * __ldg(&a[d]);
    return s;
}

// thread-level p/q write (used by k_init only)
__device__ __forceinline__ void write_pq(int t, int n, int k, const float* vec, const float* at) {
    if (t == 0) {
        g_p [(c_ROFF[0] + n) * 2 + k] = dot25(vec, at + (0 * 2 + k) * 50);
        g_qh[(c_COFF[1] + n) * 2 + k] = __float2half(dot25(vec, at + (1 * 2 + k) * 50 + 25));
    } else if (t == 1) {
        #pragma unroll
        for (int e = 1; e < 8; e++)
            g_p[(c_ROFF[e] + n) * 2 + k] = dot25(vec, at + (e * 2 + k) * 50);
        g_qh[(c_COFF[0] + n) * 2 + k] = __float2half(dot25(vec, at + (0 * 2 + k) * 50 + 25));
    } else {
        g_qh[(c_COFF[t] + n) * 2 + k] = __float2half(dot25(vec, at + (t * 2 + k) * 50 + 25));
    }
}

__device__ __forceinline__ void write_mirror(int node, int k, const float* vec) {
    __half* h = (__half*)g_embh;
    #pragma unroll
    for (int d = 0; d < 25; d++) h[(size_t)node * 2 * HS + 2 * d + k] = __float2half(vec[d]);
}

__device__ __forceinline__ float warp_sum(float v) {
    #pragma unroll
    for (int off = 16; off; off >>= 1)
        v += __shfl_xor_sync(0xffffffffu, v, off);
    return v;
}

__device__ __forceinline__ unsigned pack_half2(float a, float b) {
    __half2 h = __float22half2_rn(make_float2(a, b));
    return *reinterpret_cast<unsigned*>(&h);
}

// ---------------- initial projection + fused p/q + mirror -------------------------
__global__ void __launch_bounds__(128) k_init(Ptrs P) {
    __shared__ float Wsh[2][2][50 * 25];   // [which-type][k][d*25+f]
    int base_slot = blockIdx.x * 128;
    int node0 = base_slot >> 1;
    int nlast = (base_slot + 127) >> 1;
    if (nlast > TOTAL_NODES - 1) nlast = TOTAL_NODES - 1;
    int t0 = find_seg8(c_TOFF, node0);
    int t1 = find_seg8(c_TOFF, nlast);
    for (int i = threadIdx.x; i < 2 * 50 * 25; i += 128) {
        Wsh[0][0][i] = P.Wtk[(size_t)t0 * 2 * 50 * 25 + i];
        Wsh[1][0][i] = P.Wtk[(size_t)t1 * 2 * 50 * 25 + i];
    }
    __syncthreads();
    int slot = base_slot + threadIdx.x;
    if (slot >= TOTAL_NODES * 2) return;
    int node = slot >> 1, k = slot & 1;
    int t = find_seg8(c_TOFF, node);
    int sel = (t == t0) ? 0 : 1;
    const float* x = P.embin[t] + (size_t)(node - c_TOFF[t]) * 50;
    const float* w = &Wsh[sel][k][0];
    float out[25];
    #pragma unroll
    for (int f = 0; f < 25; f++) out[f] = 0.f;
    for (int d = 0; d < 50; d++) {
        float xd = __ldg(&x[d]);
        #pragma unroll
        for (int f = 0; f < 25; f++) out[f] += xd * w[d * 25 + f];
    }
    float nrm = 0.f;
    #pragma unroll
    for (int f = 0; f < 25; f++) {
        float s = out[f];
        s = (s >= 0.f) ? s : 0.2f * s;
        out[f] = s;
        nrm += s * s;
    }
    float inv = 1.f / fmaxf(sqrtf(nrm), 1e-12f);
    #pragma unroll
    for (int f = 0; f < 25; f++) out[f] *= inv;
    float* dst = g_emb + (size_t)node * NDIM + k * DKP;
    #pragma unroll
    for (int f = 0; f < 25; f++) dst[f] = out[f];
    dst[25] = 0.f; dst[26] = 0.f; dst[27] = 0.f;
    write_mirror(node, k, out);
    write_pq(t, node - c_TOFF[t], k, out, P.at);
}

// ---------------- CSR build: hist also records each edge's within-row rank --------
__global__ void k_hist(Ptrs P) {
    int j = blockIdx.x * blockDim.x + threadIdx.x;
    if (j >= TOTAL_EDGES) return;
    int e = find_seg8(c_EOFF, j);
    int le = j - c_EOFF[e];
    int u = P.edge[e][le];
    g_rank[j] = atomicAdd(&g_rowcnt[c_ROFF[e] + u], 1);
}

// 3-kernel scan, 8 elems/thread
__global__ void __launch_bounds__(1024) k_scanA() {
    __shared__ int sh[1024];
    int bid = blockIdx.x, tid = threadIdx.x;
    int base = bid * SCAN_ELEMS + tid * 8;
    int v[8];
    #pragma unroll
    for (int u = 0; u < 8; u++) {
        int i = base + u;
        v[u] = (i < TOTAL_ROWS) ? g_rowcnt[i] : 0;
    }
    int tsum = 0;
    #pragma unroll
    for (int u = 0; u < 8; u++) tsum += v[u];
    sh[tid] = tsum;
    __syncthreads();
    #pragma unroll
    for (int off = 1; off < 1024; off <<= 1) {
        int t = (tid >= off) ? sh[tid - off] : 0;
        __syncthreads();
        sh[tid] += t;
        __syncthreads();
    }
    int p = sh[tid] - tsum;   // local exclusive
    #pragma unroll
    for (int u = 0; u < 8; u++) {
        int i = base + u;
        if (i < TOTAL_ROWS) g_rowptr[i] = p;
        p += v[u];
    }
    if (tid == 1023) g_blocksum[bid] = sh[1023];
}

__global__ void k_scanB() {
    // 64 threads scan 33 block sums (exclusive)
    int tid = threadIdx.x;
    int v = (tid < SCAN_NBLK) ? g_blocksum[tid] : 0;
    int s = v;
    #pragma unroll
    for (int off = 1; off < 64; off <<= 1) {
        int t = __shfl_up_sync(0xffffffffu, s, off);
        if ((tid & 31) >= off) s += t;
    }
    __shared__ int w0tot;
    if (tid == 31) w0tot = s;
    __syncthreads();
    if (tid >= 32) s += w0tot;
    if (tid < SCAN_NBLK) g_blocksum[tid] = s - v;
}

__global__ void k_scanC() {
    int i = blockIdx.x * blockDim.x + threadIdx.x;
    if (i < TOTAL_ROWS) g_rowptr[i] += g_blocksum[i >> 13];
    if (i == 0) g_rowptr[TOTAL_ROWS] = TOTAL_EDGES;
}

// fill packed (cs,cq); re-zero rowcnt for the next launch (invariant: rowcnt is
// zero before every k_hist — true on first call since globals init to 0)
__global__ void k_fill(Ptrs P) {
    int j = blockIdx.x * blockDim.x + threadIdx.x;
    if (j < TOTAL_ROWS) g_rowcnt[j] = 0;
    if (j >= TOTAL_EDGES) return;
    int e = find_seg8(c_EOFF, j);
    int le = j - c_EOFF[e];
    int E = c_EOFF[e + 1] - c_EOFF[e];
    const int* ed = P.edge[e];
    int u = ed[le], c = ed[E + le];
    int row = c_ROFF[e] + u;
    int pos = g_rowptr[row] + g_rank[j];
    g_cc[pos] = make_int2((c_TOFF[c_DST[e]] + c) * HS, c_COFF[e] + c);
}

// ---------------- fused: score+softmax+aggregate+transform (warp/row) -------------
// Inner loop: HFMA2 on packed half2(w,w) * half2(f_k0,f_k1), flushed to fp32 every
// 8 edges. Transform: float4 z broadcasts (zsh 16B aligned).
__global__ void __launch_bounds__(256) k_rowtrans(Ptrs P) {
    __shared__ float Ws[625];
    __shared__ __align__(16) float zsh[8][56];  // per-warp lrelu(z): [0..24]=k0, [28..52]=k1
    __shared__ float2 wc[8][32];                // per-warp staged (packed half2 w, scaled colidx)
    for (int i = threadIdx.x; i < 625; i += 256) Ws[i] = P.W[i];
    __syncthreads();

    int row  = (blockIdx.x * 256 + threadIdx.x) >> 5;
    int lane = threadIdx.x & 31;
    int w_id = (threadIdx.x >> 5);
    bool active = (row < TOTAL_ROWS);
    int e = 0, base = 0, deg = 0;
    float2 pv = make_float2(0.f, 0.f);
    if (active) {
        e = find_seg8(c_ROFF, row);
        base = g_rowptr[row];
        deg  = g_rowptr[row + 1] - base;
        pv = ((const float2*)g_p)[row];
    }
    int dlane = (lane < 25) ? lane : 24;   // lanes 25-31 duplicate lane 24 (discarded)

    float s = 0.f;
    float accA = 0.f, accB = 0.f;          // lane d: factor0[d], factor1[d]

    const unsigned* qh32 = (const unsigned*)g_qh;
    for (int i0 = 0; i0 < deg; i0 += 32) {
        int i = i0 + lane;
        int cs = 0; float w = 0.f;
        if (i < deg) {
            int2 cc = __ldg(&g_cc[base + i]);
            cs = cc.x;
            unsigned qraw = __ldg(&qh32[cc.y]);
            float2 qv = __half22float2(*(const __half2*)&qraw);
            float v = 0.5f * (fmaxf(pv.x + qv.x, 0.f) + fmaxf(pv.y + qv.y, 0.f));
            w = __expf(v);
            s += w;
        }
        wc[w_id][lane] = make_float2(__uint_as_float(pack_half2(w, w)), __int_as_float(cs));
        __syncwarp();
        int nn = deg - i0; if (nn > 32) nn = 32;
        int nn8 = (nn + 7) & ~7;           // padded lanes: w=0, cs=0 -> harmless
        for (int j = 0; j < nn8; j += 8) {
            __half2 hacc0 = __float2half2_rn(0.f);
            __half2 hacc1 = __float2half2_rn(0.f);
            #pragma unroll
            for (int u = 0; u < 8; u += 2) {
                float2 ea = wc[w_id][j + u];
                float2 eb = wc[w_id][j + u + 1];
                unsigned wa = __float_as_uint(ea.x);
                unsigned wb = __float_as_uint(eb.x);
                unsigned ha = __ldg(&g_embh[__float_as_int(ea.y) + dlane]);
                unsigned hb = __ldg(&g_embh[__float_as_int(eb.y) + dlane]);
                hacc0 = __hfma2(*(const __half2*)&wa, *(const __half2*)&ha, hacc0);
                hacc1 = __hfma2(*(const __half2*)&wb, *(const __half2*)&hb, hacc1);
            }
            float2 fa = __half22float2(hacc0);
            float2 fb = __half22float2(hacc1);
            accA += fa.x + fb.x;
            accB += fa.y + fb.y;
        }
        __syncwarp();
    }
    s = warp_sum(s);
    float invS = (deg > 0) ? (1.f / s) : 0.f;

    if (lane < 25) {
        float zx = accA * invS;
        float zy = accB * invS;
        zsh[w_id][lane]      = (zx >= 0.f) ? zx : 0.2f * zx;
        zsh[w_id][28 + lane] = (zy >= 0.f) ? zy : 0.2f * zy;
    }
    __syncwarp();

    // transform: lane f<25 computes out[k][f] = sum_d zsh[k][d]*W[d][f]
    float out0 = 0.f, out1 = 0.f;
    if (lane < 25) {
        const float4* z0q = (const float4*)&zsh[w_id][0];
        const float4* z1q = (const float4*)&zsh[w_id][28];
        #pragma unroll
        for (int dq = 0; dq < 6; dq++) {
            float4 a = z0q[dq];
            float4 b = z1q[dq];
            int d = dq * 4;
            float w0 = Ws[(d + 0) * 25 + lane];
            float w1 = Ws[(d + 1) * 25 + lane];
            float w2 = Ws[(d + 2) * 25 + lane];
            float w3 = Ws[(d + 3) * 25 + lane];
            out0 += a.x * w0 + a.y * w1 + a.z * w2 + a.w * w3;
            out1 += b.x * w0 + b.y * w1 + b.z * w2 + b.w * w3;
        }
        float w24 = Ws[24 * 25 + lane];
        out0 += zsh[w_id][24] * w24;
        out1 += zsh[w_id][28 + 24] * w24;
    }
    float qrf = (active && lane < 25) ? __ldg(&P.q_rela[e * 25 + lane]) : 0.f;
    float p0 = fast_tanh(out0) * qrf;
    float p1 = fast_tanh(out1) * qrf;
    if (lane >= 25) { p0 = 0.f; p1 = 0.f; }
    p0 = warp_sum(p0);
    p1 = warp_sum(p1);
    if (active) {
        if (lane == 0) {
            float mm = fmaxf(p0, p1);
            float e0 = __expf(p0 - mm), e1 = __expf(p1 - mm);
            float inv = 1.f / (e0 + e1);
            ((float2*)g_r)[row] = make_float2(e0 * inv, e1 * inv);
        }
        float* zr = g_z + (size_t)row * NDIM;
        if (lane < 25) {
            zr[lane] = out0;
            zr[DKP + lane] = out1;
        }
    }
}

// ---------------- warp-per-node ego aggregation + normalize -----------------------
// Non-last iters: update g_emb + mirror + p/q. Last iter: write d_out directly
// (k_init fully rewrites emb/mirror/p/q each launch, so skipping them is safe).
__global__ void __launch_bounds__(256) k_agg(Ptrs P, float* __restrict__ out, int last) {
    int node = (blockIdx.x * 256 + threadIdx.x) >> 5;
    int lane = threadIdx.x & 31;
    if (node >= OUT_ROWS) return;
    bool ld = (lane < 25);
    float* er = g_emb + (size_t)node * NDIM;
    float a0 = 0.f, a1 = 0.f;
    if (ld) { a0 = er[lane]; a1 = er[DKP + lane]; }
    if (node < 60000) {                 // type 0: relation 0 only
        float2 r = ((const float2*)g_r)[node];
        const float* zz = g_z + (size_t)node * NDIM;
        if (ld) { a0 += r.x * zz[lane]; a1 += r.y * zz[DKP + lane]; }
    } else {                            // type 1: relations 1..7
        int n = node - 60000;
        #pragma unroll
        for (int e = 1; e < 8; e++) {
            int row = c_ROFF[e] + n;
            float2 r = ((const float2*)g_r)[row];
            const float* zz = g_z + (size_t)row * NDIM;
            if (ld) { a0 += r.x * zz[lane]; a1 += r.y * zz[DKP + lane]; }
        }
    }
    float n0 = warp_sum(a0 * a0);
    float n1 = warp_sum(a1 * a1);
    a0 *= 1.f / fmaxf(sqrtf(n0), 1e-12f);
    a1 *= 1.f / fmaxf(sqrtf(n1), 1e-12f);

    if (last) {
        if (ld) {
            out[(size_t)node * 50 + lane]      = a0;
            out[(size_t)node * 50 + 25 + lane] = a1;
        }
        return;
    }

    if (ld) {
        er[lane] = a0;
        er[DKP + lane] = a1;
        g_embh[(size_t)node * HS + lane] = pack_half2(a0, a1);
    }
    // p/q dots: type0 -> p(rel0), q(rel1); type1 -> p(rel1..7), q(rel0)
    const float* at = P.at;
    if (node < 60000) {
        int n = node;
        #pragma unroll
        for (int k = 0; k < 2; k++) {
            float ak = k ? a1 : a0;
            float dp = warp_sum(ld ? ak * __ldg(&at[(0 * 2 + k) * 50 + lane]) : 0.f);
            float dq = warp_sum(ld ? ak * __ldg(&at[(1 * 2 + k) * 50 + 25 + lane]) : 0.f);
            if (lane == 0) {
                g_p [(c_ROFF[0] + n) * 2 + k] = dp;
                g_qh[(c_COFF[1] + n) * 2 + k] = __float2half(dq);
            }
        }
    } else {
        int n = node - 60000;
        #pragma unroll
        for (int k = 0; k < 2; k++) {
            float ak = k ? a1 : a0;
            #pragma unroll
            for (int e = 1; e < 8; e++) {
                float dp = warp_sum(ld ? ak * __ldg(&at[(e * 2 + k) * 50 + lane]) : 0.f);
                if (lane == 0) g_p[(c_ROFF[e] + n) * 2 + k] = dp;
            }
            float dq = warp_sum(ld ? ak * __ldg(&at[(0 * 2 + k) * 50 + 25 + lane]) : 0.f);
            if (lane == 0) g_qh[(c_COFF[0] + n) * 2 + k] = __float2half(dq);
        }
    }
}

} // anonymous namespace

extern "C" void kernel_launch(void* const* d_in, const int* in_sizes, int n_in,
                              void* d_out, int out_size) {
    Ptrs P;
    for (int i = 0; i < 8; i++) P.edge[i]  = (const int*)d_in[i];
    for (int i = 0; i < 8; i++) P.embin[i] = (const float*)d_in[8 + i];
    P.Wtk    = (const float*)d_in[16];
    P.at     = (const float*)d_in[17];
    P.W      = (const float*)d_in[18];
    P.q_rela = (const float*)d_in[19];

    k_init<<<(TOTAL_NODES * 2 + 127) / 128, 128>>>(P);
    k_hist<<<(TOTAL_EDGES + 255) / 256, 256>>>(P);
    k_scanA<<<SCAN_NBLK, 1024>>>();
    k_scanB<<<1, 64>>>();
    k_scanC<<<(TOTAL_ROWS + 255) / 256, 256>>>();
    k_fill<<<(TOTAL_EDGES + 255) / 256, 256>>>(P);

    for (int it = 0; it < 4; it++) {
        k_rowtrans<<<(TOTAL_ROWS * 32 + 255) / 256, 256>>>(P);
        k_agg<<<(OUT_ROWS * 32 + 255) / 256, 256>>>(P, (float*)d_out, it == 3);
    }
}

// round 17
// speedup vs baseline: 1.1310x; 1.1310x over previous
#include <cuda_runtime.h>
#include <cuda_fp16.h>
#include <math.h>

namespace {

constexpr int DKP = 28;              // padded factor dim (25 -> 28), fp32 master
constexpr int NDIM = 2 * DKP;        // 56 floats per node (fp32 master)
constexpr int HS   = 32;             // half2 stride per node in fp16 mirror (128B aligned)
constexpr int TOTAL_NODES = 180000;  // 60000 + 30000 + 6*15000
constexpr int TOTAL_ROWS  = 270000;  // 60000 + 7*30000
constexpr int TOTAL_COLS  = 180000;  // 30000 + 60000 + 6*15000
constexpr int TOTAL_EDGES = 3800000; // 2*1e6 + 6*3e5
constexpr int OUT_ROWS = 90000;
constexpr int SCAN_ELEMS = 8192;     // per block (1024 thr x 8)
constexpr int SCAN_NBLK = (TOTAL_ROWS + SCAN_ELEMS - 1) / SCAN_ELEMS; // 33

__constant__ int c_EOFF[9] = {0,1000000,2000000,2300000,2600000,2900000,3200000,3500000,3800000};
__constant__ int c_ROFF[9] = {0,60000,90000,120000,150000,180000,210000,240000,270000};
__constant__ int c_COFF[9] = {0,30000,90000,105000,120000,135000,150000,165000,180000};
__constant__ int c_TOFF[9] = {0,60000,90000,105000,120000,135000,150000,165000,180000};
__constant__ int c_SRC[8]  = {0,1,1,1,1,1,1,1};
__constant__ int c_DST[8]  = {1,0,2,3,4,5,6,7};

__device__ float    g_emb [(size_t)TOTAL_NODES * NDIM + 16]; // fp32 master
__device__ unsigned g_embh[(size_t)TOTAL_NODES * HS];        // fp16 mirror: half2(k0[d],k1[d]), 128B rows
__device__ float    g_z   [(size_t)TOTAL_ROWS  * NDIM];      // transformed messages z'
__device__ float    g_p   [TOTAL_ROWS * 2];
__device__ __half   g_qh  [TOTAL_COLS * 2];                  // fp16 q, pair-packed
__device__ float    g_r   [TOTAL_ROWS * 2];
__device__ int      g_rowcnt[TOTAL_ROWS];        // re-zeroed by k_fill (invariant)
__device__ int      g_rowptr[TOTAL_ROWS + 1];
__device__ int      g_blocksum[SCAN_NBLK];
__device__ int      g_rank  [TOTAL_EDGES];
__device__ int2     g_cc    [TOTAL_EDGES];       // (pre-scaled mirror idx, pre-offset q idx)

struct Ptrs {
    const int*   edge[8];
    const float* embin[8];
    const float* Wtk;
    const float* at;
    const float* W;
    const float* q_rela;
};

__device__ __forceinline__ int find_seg8(const int* off, int x) {
    int e = 0;
    #pragma unroll
    for (int i = 1; i < 8; i++) e += (x >= off[i]);
    return e;
}

__device__ __forceinline__ float fast_tanh(float x) {
    float y;
    asm("tanh.approx.f32 %0, %1;" : "=f"(y) : "f"(x));
    return y;
}

__device__ __forceinline__ float dot25(const float* v, const float* a) {
    float s = 0.f;
    #pragma unroll
    for (int d = 0; d < 25; d++) s += v[d] * __ldg(&a[d]);
    return s;
}

// thread-level p/q write (used by k_init only)
__device__ __forceinline__ void write_pq(int t, int n, int k, const float* vec, const float* at) {
    if (t == 0) {
        g_p [(c_ROFF[0] + n) * 2 + k] = dot25(vec, at + (0 * 2 + k) * 50);
        g_qh[(c_COFF[1] + n) * 2 + k] = __float2half(dot25(vec, at + (1 * 2 + k) * 50 + 25));
    } else if (t == 1) {
        #pragma unroll
        for (int e = 1; e < 8; e++)
            g_p[(c_ROFF[e] + n) * 2 + k] = dot25(vec, at + (e * 2 + k) * 50);
        g_qh[(c_COFF[0] + n) * 2 + k] = __float2half(dot25(vec, at + (0 * 2 + k) * 50 + 25));
    } else {
        g_qh[(c_COFF[t] + n) * 2 + k] = __float2half(dot25(vec, at + (t * 2 + k) * 50 + 25));
    }
}

__device__ __forceinline__ void write_mirror(int node, int k, const float* vec) {
    __half* h = (__half*)g_embh;
    #pragma unroll
    for (int d = 0; d < 25; d++) h[(size_t)node * 2 * HS + 2 * d + k] = __float2half(vec[d]);
}

__device__ __forceinline__ float warp_sum(float v) {
    #pragma unroll
    for (int off = 16; off; off >>= 1)
        v += __shfl_xor_sync(0xffffffffu, v, off);
    return v;
}

__device__ __forceinline__ unsigned pack_half2(float a, float b) {
    __half2 h = __float22half2_rn(make_float2(a, b));
    return *reinterpret_cast<unsigned*>(&h);
}

// ---------------- initial projection + fused p/q + mirror -------------------------
__global__ void __launch_bounds__(128) k_init(Ptrs P) {
    __shared__ float Wsh[2][2][50 * 25];   // [which-type][k][d*25+f]
    int base_slot = blockIdx.x * 128;
    int node0 = base_slot >> 1;
    int nlast = (base_slot + 127) >> 1;
    if (nlast > TOTAL_NODES - 1) nlast = TOTAL_NODES - 1;
    int t0 = find_seg8(c_TOFF, node0);
    int t1 = find_seg8(c_TOFF, nlast);
    for (int i = threadIdx.x; i < 2 * 50 * 25; i += 128) {
        Wsh[0][0][i] = P.Wtk[(size_t)t0 * 2 * 50 * 25 + i];
        Wsh[1][0][i] = P.Wtk[(size_t)t1 * 2 * 50 * 25 + i];
    }
    __syncthreads();
    int slot = base_slot + threadIdx.x;
    if (slot >= TOTAL_NODES * 2) return;
    int node = slot >> 1, k = slot & 1;
    int t = find_seg8(c_TOFF, node);
    int sel = (t == t0) ? 0 : 1;
    const float* x = P.embin[t] + (size_t)(node - c_TOFF[t]) * 50;
    const float* w = &Wsh[sel][k][0];
    float out[25];
    #pragma unroll
    for (int f = 0; f < 25; f++) out[f] = 0.f;
    for (int d = 0; d < 50; d++) {
        float xd = __ldg(&x[d]);
        #pragma unroll
        for (int f = 0; f < 25; f++) out[f] += xd * w[d * 25 + f];
    }
    float nrm = 0.f;
    #pragma unroll
    for (int f = 0; f < 25; f++) {
        float s = out[f];
        s = (s >= 0.f) ? s : 0.2f * s;
        out[f] = s;
        nrm += s * s;
    }
    float inv = 1.f / fmaxf(sqrtf(nrm), 1e-12f);
    #pragma unroll
    for (int f = 0; f < 25; f++) out[f] *= inv;
    float* dst = g_emb + (size_t)node * NDIM + k * DKP;
    #pragma unroll
    for (int f = 0; f < 25; f++) dst[f] = out[f];
    dst[25] = 0.f; dst[26] = 0.f; dst[27] = 0.f;
    write_mirror(node, k, out);
    write_pq(t, node - c_TOFF[t], k, out, P.at);
}

// ---------------- CSR build: hist also records each edge's within-row rank --------
__global__ void k_hist(Ptrs P) {
    int j = blockIdx.x * blockDim.x + threadIdx.x;
    if (j >= TOTAL_EDGES) return;
    int e = find_seg8(c_EOFF, j);
    int le = j - c_EOFF[e];
    int u = P.edge[e][le];
    g_rank[j] = atomicAdd(&g_rowcnt[c_ROFF[e] + u], 1);
}

// 3-kernel scan, 8 elems/thread
__global__ void __launch_bounds__(1024) k_scanA() {
    __shared__ int sh[1024];
    int bid = blockIdx.x, tid = threadIdx.x;
    int base = bid * SCAN_ELEMS + tid * 8;
    int v[8];
    #pragma unroll
    for (int u = 0; u < 8; u++) {
        int i = base + u;
        v[u] = (i < TOTAL_ROWS) ? g_rowcnt[i] : 0;
    }
    int tsum = 0;
    #pragma unroll
    for (int u = 0; u < 8; u++) tsum += v[u];
    sh[tid] = tsum;
    __syncthreads();
    #pragma unroll
    for (int off = 1; off < 1024; off <<= 1) {
        int t = (tid >= off) ? sh[tid - off] : 0;
        __syncthreads();
        sh[tid] += t;
        __syncthreads();
    }
    int p = sh[tid] - tsum;   // local exclusive
    #pragma unroll
    for (int u = 0; u < 8; u++) {
        int i = base + u;
        if (i < TOTAL_ROWS) g_rowptr[i] = p;
        p += v[u];
    }
    if (tid == 1023) g_blocksum[bid] = sh[1023];
}

__global__ void k_scanB() {
    // 64 threads scan 33 block sums (exclusive)
    int tid = threadIdx.x;
    int v = (tid < SCAN_NBLK) ? g_blocksum[tid] : 0;
    int s = v;
    #pragma unroll
    for (int off = 1; off < 64; off <<= 1) {
        int t = __shfl_up_sync(0xffffffffu, s, off);
        if ((tid & 31) >= off) s += t;
    }
    __shared__ int w0tot;
    if (tid == 31) w0tot = s;
    __syncthreads();
    if (tid >= 32) s += w0tot;
    if (tid < SCAN_NBLK) g_blocksum[tid] = s - v;
}

__global__ void k_scanC() {
    int i = blockIdx.x * blockDim.x + threadIdx.x;
    if (i < TOTAL_ROWS) g_rowptr[i] += g_blocksum[i >> 13];
    if (i == 0) g_rowptr[TOTAL_ROWS] = TOTAL_EDGES;
}

// fill packed (cs,cq); re-zero rowcnt for the next launch (invariant: rowcnt is
// zero before every k_hist — true on first call since globals init to 0)
__global__ void k_fill(Ptrs P) {
    int j = blockIdx.x * blockDim.x + threadIdx.x;
    if (j < TOTAL_ROWS) g_rowcnt[j] = 0;
    if (j >= TOTAL_EDGES) return;
    int e = find_seg8(c_EOFF, j);
    int le = j - c_EOFF[e];
    int E = c_EOFF[e + 1] - c_EOFF[e];
    const int* ed = P.edge[e];
    int u = ed[le], c = ed[E + le];
    int row = c_ROFF[e] + u;
    int pos = g_rowptr[row] + g_rank[j];
    g_cc[pos] = make_int2((c_TOFF[c_DST[e]] + c) * HS, c_COFF[e] + c);
}

// ---------------- fused: score+softmax+aggregate+transform (warp/row) -------------
// R14 aggregation loop (proven). Transform: float4 z broadcasts (zsh 16B aligned).
__global__ void __launch_bounds__(256) k_rowtrans(Ptrs P) {
    __shared__ float Ws[625];
    __shared__ __align__(16) float zsh[8][56];  // per-warp lrelu(z): [0..24]=k0, [28..52]=k1
    __shared__ float2 wc[8][32];                // per-warp staged (weight, scaled colidx)
    for (int i = threadIdx.x; i < 625; i += 256) Ws[i] = P.W[i];
    __syncthreads();

    int row  = (blockIdx.x * 256 + threadIdx.x) >> 5;
    int lane = threadIdx.x & 31;
    int w_id = (threadIdx.x >> 5);
    bool active = (row < TOTAL_ROWS);
    int e = 0, base = 0, deg = 0;
    float2 pv = make_float2(0.f, 0.f);
    if (active) {
        e = find_seg8(c_ROFF, row);
        base = g_rowptr[row];
        deg  = g_rowptr[row + 1] - base;
        pv = ((const float2*)g_p)[row];
    }
    int dlane = (lane < 25) ? lane : 24;   // lanes 25-31 duplicate lane 24 (discarded)

    float s = 0.f;
    float accA = 0.f, accB = 0.f;          // lane d: factor0[d], factor1[d]

    const unsigned* qh32 = (const unsigned*)g_qh;
    for (int i0 = 0; i0 < deg; i0 += 32) {
        int i = i0 + lane;
        int cs = 0; float w = 0.f;
        if (i < deg) {
            int2 cc = __ldg(&g_cc[base + i]);
            cs = cc.x;
            unsigned qraw = __ldg(&qh32[cc.y]);
            float2 qv = __half22float2(*(const __half2*)&qraw);
            float v = 0.5f * (fmaxf(pv.x + qv.x, 0.f) + fmaxf(pv.y + qv.y, 0.f));
            w = __expf(v);
            s += w;
        }
        wc[w_id][lane] = make_float2(w, __int_as_float(cs));
        __syncwarp();
        int nn = deg - i0; if (nn > 32) nn = 32;
        int nn4 = (nn + 3) & ~3;           // padded lanes: w=0, cs=0 -> harmless
        for (int j = 0; j < nn4; j += 4) {
            float2 e0 = wc[w_id][j + 0];
            float2 e1 = wc[w_id][j + 1];
            float2 e2 = wc[w_id][j + 2];
            float2 e3 = wc[w_id][j + 3];
            unsigned h0 = __ldg(&g_embh[__float_as_int(e0.y) + dlane]);
            unsigned h1 = __ldg(&g_embh[__float_as_int(e1.y) + dlane]);
            unsigned h2 = __ldg(&g_embh[__float_as_int(e2.y) + dlane]);
            unsigned h3 = __ldg(&g_embh[__float_as_int(e3.y) + dlane]);
            float2 f0 = __half22float2(*(const __half2*)&h0);
            float2 f1 = __half22float2(*(const __half2*)&h1);
            float2 f2 = __half22float2(*(const __half2*)&h2);
            float2 f3 = __half22float2(*(const __half2*)&h3);
            accA += e0.x * f0.x; accB += e0.x * f0.y;
            accA += e1.x * f1.x; accB += e1.x * f1.y;
            accA += e2.x * f2.x; accB += e2.x * f2.y;
            accA += e3.x * f3.x; accB += e3.x * f3.y;
        }
        __syncwarp();
    }
    s = warp_sum(s);
    float invS = (deg > 0) ? (1.f / s) : 0.f;

    if (lane < 25) {
        float zx = accA * invS;
        float zy = accB * invS;
        zsh[w_id][lane]      = (zx >= 0.f) ? zx : 0.2f * zx;
        zsh[w_id][28 + lane] = (zy >= 0.f) ? zy : 0.2f * zy;
    }
    __syncwarp();

    // transform: lane f<25 computes out[k][f] = sum_d zsh[k][d]*W[d][f]
    float out0 = 0.f, out1 = 0.f;
    if (lane < 25) {
        const float4* z0q = (const float4*)&zsh[w_id][0];
        const float4* z1q = (const float4*)&zsh[w_id][28];
        #pragma unroll
        for (int dq = 0; dq < 6; dq++) {
            float4 a = z0q[dq];
            float4 b = z1q[dq];
            int d = dq * 4;
            float w0 = Ws[(d + 0) * 25 + lane];
            float w1 = Ws[(d + 1) * 25 + lane];
            float w2 = Ws[(d + 2) * 25 + lane];
            float w3 = Ws[(d + 3) * 25 + lane];
            out0 += a.x * w0 + a.y * w1 + a.z * w2 + a.w * w3;
            out1 += b.x * w0 + b.y * w1 + b.z * w2 + b.w * w3;
        }
        float w24 = Ws[24 * 25 + lane];
        out0 += zsh[w_id][24] * w24;
        out1 += zsh[w_id][28 + 24] * w24;
    }
    float qrf = (active && lane < 25) ? __ldg(&P.q_rela[e * 25 + lane]) : 0.f;
    float p0 = fast_tanh(out0) * qrf;
    float p1 = fast_tanh(out1) * qrf;
    if (lane >= 25) { p0 = 0.f; p1 = 0.f; }
    p0 = warp_sum(p0);
    p1 = warp_sum(p1);
    if (active) {
        if (lane == 0) {
            float mm = fmaxf(p0, p1);
            float e0 = __expf(p0 - mm), e1 = __expf(p1 - mm);
            float inv = 1.f / (e0 + e1);
            ((float2*)g_r)[row] = make_float2(e0 * inv, e1 * inv);
        }
        float* zr = g_z + (size_t)row * NDIM;
        if (lane < 25) {
            zr[lane] = out0;
            zr[DKP + lane] = out1;
        }
    }
}

// ---------------- warp-per-node ego aggregation + normalize -----------------------
// Non-last iters: update g_emb + mirror + p/q. Last iter: write d_out directly
// (k_init fully rewrites emb/mirror/p/q each launch, so skipping them is safe).
__global__ void __launch_bounds__(256) k_agg(Ptrs P, float* __restrict__ out, int last) {
    int node = (blockIdx.x * 256 + threadIdx.x) >> 5;
    int lane = threadIdx.x & 31;
    if (node >= OUT_ROWS) return;
    bool ld = (lane < 25);
    float* er = g_emb + (size_t)node * NDIM;
    float a0 = 0.f, a1 = 0.f;
    if (ld) { a0 = er[lane]; a1 = er[DKP + lane]; }
    if (node < 60000) {                 // type 0: relation 0 only
        float2 r = ((const float2*)g_r)[node];
        const float* zz = g_z + (size_t)node * NDIM;
        if (ld) { a0 += r.x * zz[lane]; a1 += r.y * zz[DKP + lane]; }
    } else {                            // type 1: relations 1..7
        int n = node - 60000;
        #pragma unroll
        for (int e = 1; e < 8; e++) {
            int row = c_ROFF[e] + n;
            float2 r = ((const float2*)g_r)[row];
            const float* zz = g_z + (size_t)row * NDIM;
            if (ld) { a0 += r.x * zz[lane]; a1 += r.y * zz[DKP + lane]; }
        }
    }
    float n0 = warp_sum(a0 * a0);
    float n1 = warp_sum(a1 * a1);
    a0 *= 1.f / fmaxf(sqrtf(n0), 1e-12f);
    a1 *= 1.f / fmaxf(sqrtf(n1), 1e-12f);

    if (last) {
        if (ld) {
            out[(size_t)node * 50 + lane]      = a0;
            out[(size_t)node * 50 + 25 + lane] = a1;
        }
        return;
    }

    if (ld) {
        er[lane] = a0;
        er[DKP + lane] = a1;
        g_embh[(size_t)node * HS + lane] = pack_half2(a0, a1);
    }
    // p/q dots: type0 -> p(rel0), q(rel1); type1 -> p(rel1..7), q(rel0)
    const float* at = P.at;
    if (node < 60000) {
        int n = node;
        #pragma unroll
        for (int k = 0; k < 2; k++) {
            float ak = k ? a1 : a0;
            float dp = warp_sum(ld ? ak * __ldg(&at[(0 * 2 + k) * 50 + lane]) : 0.f);
            float dq = warp_sum(ld ? ak * __ldg(&at[(1 * 2 + k) * 50 + 25 + lane]) : 0.f);
            if (lane == 0) {
                g_p [(c_ROFF[0] + n) * 2 + k] = dp;
                g_qh[(c_COFF[1] + n) * 2 + k] = __float2half(dq);
            }
        }
    } else {
        int n = node - 60000;
        #pragma unroll
        for (int k = 0; k < 2; k++) {
            float ak = k ? a1 : a0;
            #pragma unroll
            for (int e = 1; e < 8; e++) {
                float dp = warp_sum(ld ? ak * __ldg(&at[(e * 2 + k) * 50 + lane]) : 0.f);
                if (lane == 0) g_p[(c_ROFF[e] + n) * 2 + k] = dp;
            }
            float dq = warp_sum(ld ? ak * __ldg(&at[(0 * 2 + k) * 50 + 25 + lane]) : 0.f);
            if (lane == 0) g_qh[(c_COFF[0] + n) * 2 + k] = __float2half(dq);
        }
    }
}

} // anonymous namespace

extern "C" void kernel_launch(void* const* d_in, const int* in_sizes, int n_in,
                              void* d_out, int out_size) {
    Ptrs P;
    for (int i = 0; i < 8; i++) P.edge[i]  = (const int*)d_in[i];
    for (int i = 0; i < 8; i++) P.embin[i] = (const float*)d_in[8 + i];
    P.Wtk    = (const float*)d_in[16];
    P.at     = (const float*)d_in[17];
    P.W      = (const float*)d_in[18];
    P.q_rela = (const float*)d_in[19];

    k_init<<<(TOTAL_NODES * 2 + 127) / 128, 128>>>(P);
    k_hist<<<(TOTAL_EDGES + 255) / 256, 256>>>(P);
    k_scanA<<<SCAN_NBLK, 1024>>>();
    k_scanB<<<1, 64>>>();
    k_scanC<<<(TOTAL_ROWS + 255) / 256, 256>>>();
    k_fill<<<(TOTAL_EDGES + 255) / 256, 256>>>(P);

    for (int it = 0; it < 4; it++) {
        k_rowtrans<<<(TOTAL_ROWS * 32 + 255) / 256, 256>>>(P);
        k_agg<<<(OUT_ROWS * 32 + 255) / 256, 256>>>(P, (float*)d_out, it == 3);
    }
}